// round 2
// baseline (speedup 1.0000x reference)
#include <cuda_runtime.h>
#include <stdint.h>

// =====================================================================
// RANSAC homography (JAX reference reproduction) for GB300 / sm_103a
//
// Pipeline:
//   k_sample : threefry2x32 uniforms + exact top-4 per (iter,batch) row
//   k_dlt    : 4-point DLT homography (fp64 nullspace solve) + Hinv + valid
//   k_score  : symmetric transfer error inlier count per model (f32, like ref)
//   k_reduce : global argmax (score desc, model-id asc), threshold score>1
//   k_out    : write [H(9), inlier mask(10000)] as float32
//
// JAX PRNG: threefry2x32. JAX >= 0.4.36 defaults to the *partitionable*
// bit-generation path. Flip this macro to 0 if rel_err indicates the
// container runs the legacy (original) path.
#define JAX_PARTITIONABLE 1
// =====================================================================

#define N_PTS    10000
#define BATCH    2048
#define MAX_ITER 10
#define NMODELS  (BATCH * MAX_ITER)
#define HALF_CNT 10240000u   // (BATCH*N_PTS)/2 for the legacy split layout

// -------- scratch (no cudaMalloc allowed) ----------------------------
__device__ int   g_idx[NMODELS * 4];
__device__ float g_H[NMODELS * 9];
__device__ float g_Hinv[NMODELS * 9];
__device__ int   g_score[NMODELS];   // -1 invalid, else inlier count
__device__ int   g_bestid;           // -1 => fall back to identity/zeros

struct KeyList { uint32_t k0[MAX_ITER]; uint32_t k1[MAX_ITER]; };

// -------- threefry2x32 core (matches jax._src.prng exactly) ----------
__host__ __device__ inline void tf2x32(uint32_t k0, uint32_t k1,
                                       uint32_t x0, uint32_t x1,
                                       uint32_t& o0, uint32_t& o1) {
  const uint32_t ks2 = k0 ^ k1 ^ 0x1BD11BDAu;
  x0 += k0; x1 += k1;
#define TF_R(r) { x0 += x1; x1 = (x1 << (r)) | (x1 >> (32 - (r))); x1 ^= x0; }
  TF_R(13) TF_R(15) TF_R(26) TF_R(6)
  x0 += k1;  x1 += ks2 + 1u;
  TF_R(17) TF_R(29) TF_R(16) TF_R(24)
  x0 += ks2; x1 += k0 + 2u;
  TF_R(13) TF_R(15) TF_R(26) TF_R(6)
  x0 += k0;  x1 += k1 + 3u;
  TF_R(17) TF_R(29) TF_R(16) TF_R(24)
  x0 += k1;  x1 += ks2 + 4u;
  TF_R(13) TF_R(15) TF_R(26) TF_R(6)
  x0 += ks2; x1 += k0 + 5u;
#undef TF_R
  o0 = x0; o1 = x1;
}

// lexicographic comparator matching jax.lax.top_k tie rule
__device__ __forceinline__ bool better(float v1, int i1, float v2, int i2) {
  return (v1 > v2) || (v1 == v2 && i1 < i2);
}

// =====================================================================
// Kernel 1: per (iter, batch-row) exact top-4 of 10000 uniforms
// =====================================================================
__global__ __launch_bounds__(256) void k_sample(KeyList keys) {
  const int b   = blockIdx.x;   // batch row 0..2047
  const int it  = blockIdx.y;   // iteration 0..9
  const int tid = threadIdx.x;
  const uint32_t kk0 = keys.k0[it];
  const uint32_t kk1 = keys.k1[it];

  float v[4]  = {-1.f, -1.f, -1.f, -1.f};
  int   idn[4] = {0x7fffffff, 0x7fffffff, 0x7fffffff, 0x7fffffff};

  for (int j = tid; j < N_PTS; j += 256) {
    uint32_t bits;
#if JAX_PARTITIONABLE
    // partitionable: counts = (hi,lo) of 64-bit flat index; bits = y0 ^ y1
    uint32_t y0, y1;
    tf2x32(kk0, kk1, 0u, (uint32_t)(b * N_PTS + j), y0, y1);
    bits = y0 ^ y1;
#else
    // legacy: flat array split in halves; first half -> y0, second -> y1
    uint32_t i = (uint32_t)(b * N_PTS + j);
    uint32_t y0, y1;
    if (i < HALF_CNT) { tf2x32(kk0, kk1, i, i + HALF_CNT, y0, y1); bits = y0; }
    else              { tf2x32(kk0, kk1, i - HALF_CNT, i, y0, y1); bits = y1; }
#endif
    // jax.random.uniform: mantissa-fill trick
    float u = __uint_as_float((bits >> 9) | 0x3f800000u) - 1.0f;

    // top-4 insert (fast-path single compare)
    if (u > v[3] || (u == v[3] && j < idn[3])) {
      v[3] = u; idn[3] = j;
#pragma unroll
      for (int p = 3; p >= 1; p--) {
        if (better(v[p], idn[p], v[p-1], idn[p-1])) {
          float tv = v[p]; v[p] = v[p-1]; v[p-1] = tv;
          int   ti = idn[p]; idn[p] = idn[p-1]; idn[p-1] = ti;
        }
      }
    }
  }

  // block tree-merge of sorted 4-lists
  __shared__ float sv[256][4];
  __shared__ int   si[256][4];
#pragma unroll
  for (int t = 0; t < 4; t++) { sv[tid][t] = v[t]; si[tid][t] = idn[t]; }
  __syncthreads();
  for (int s = 128; s >= 1; s >>= 1) {
    if (tid < s) {
      float ov[4]; int oi[4];
      int pa = 0, pb = 0;
#pragma unroll
      for (int t = 0; t < 4; t++) {
        float av = sv[tid][pa],     bv = sv[tid + s][pb];
        int   ai = si[tid][pa],     bi = si[tid + s][pb];
        if (better(av, ai, bv, bi)) { ov[t] = av; oi[t] = ai; pa++; }
        else                        { ov[t] = bv; oi[t] = bi; pb++; }
      }
#pragma unroll
      for (int t = 0; t < 4; t++) { sv[tid][t] = ov[t]; si[tid][t] = oi[t]; }
    }
    __syncthreads();
  }
  if (tid < 4) g_idx[((it * BATCH) + b) * 4 + tid] = si[0][tid];
}

// =====================================================================
// Kernel 2: DLT homography per model (fp64), + Hinv + validity
// =====================================================================
__global__ __launch_bounds__(128) void k_dlt(const float* __restrict__ kp1,
                                             const float* __restrict__ kp2) {
  const int m = blockIdx.x * blockDim.x + threadIdx.x;
  if (m >= NMODELS) return;

  double px[4], py[4], qx[4], qy[4];
#pragma unroll
  for (int t = 0; t < 4; t++) {
    int j = g_idx[m * 4 + t];
    px[t] = (double)kp1[2*j]; py[t] = (double)kp1[2*j+1];
    qx[t] = (double)kp2[2*j]; qy[t] = (double)kp2[2*j+1];
  }

  // normalize_points (reference semantics, in fp64)
  double m1x = 0.25*(px[0]+px[1]+px[2]+px[3]);
  double m1y = 0.25*(py[0]+py[1]+py[2]+py[3]);
  double m2x = 0.25*(qx[0]+qx[1]+qx[2]+qx[3]);
  double m2y = 0.25*(qy[0]+qy[1]+qy[2]+qy[3]);
  double d1 = 0.0, d2 = 0.0;
#pragma unroll
  for (int t = 0; t < 4; t++) {
    double ax = px[t]-m1x, ay = py[t]-m1y;
    double bx = qx[t]-m2x, by = qy[t]-m2y;
    d1 += sqrt(ax*ax + ay*ay);
    d2 += sqrt(bx*bx + by*by);
  }
  d1 *= 0.25; d2 *= 0.25;
  const double SQ2 = 1.4142135623730951;
  double s1 = SQ2 / (d1 + 1e-8);
  double s2 = SQ2 / (d2 + 1e-8);

  double x1[4], y1v[4], x2[4], y2v[4];
#pragma unroll
  for (int t = 0; t < 4; t++) {
    x1[t]  = (px[t]-m1x)*s1;  y1v[t] = (py[t]-m1y)*s1;
    x2[t]  = (qx[t]-m2x)*s2;  y2v[t] = (qy[t]-m2y)*s2;
  }

  // A (8x9): ax rows then ay rows (row order irrelevant for nullspace)
  double A[8][9];
#pragma unroll
  for (int t = 0; t < 4; t++) {
    double xx = x1[t], yy = y1v[t], XX = x2[t], YY = y2v[t];
    A[t][0]=0;  A[t][1]=0;  A[t][2]=0;
    A[t][3]=-xx; A[t][4]=-yy; A[t][5]=-1.0;
    A[t][6]=YY*xx; A[t][7]=YY*yy; A[t][8]=YY;
    A[4+t][0]=xx; A[4+t][1]=yy; A[4+t][2]=1.0;
    A[4+t][3]=0;  A[4+t][4]=0;  A[4+t][5]=0;
    A[4+t][6]=-XX*xx; A[4+t][7]=-XX*yy; A[4+t][8]=-XX;
  }

  // Gaussian elimination w/ partial pivoting -> 1-D nullspace vector
  int pivcol[8];
  bool isfree[9];
  for (int c = 0; c < 9; c++) isfree[c] = true;
  int r = 0;
  for (int c = 0; c < 9 && r < 8; c++) {
    int pr = r; double pv = fabs(A[r][c]);
    for (int i2 = r + 1; i2 < 8; i2++) {
      double a = fabs(A[i2][c]);
      if (a > pv) { pv = a; pr = i2; }
    }
    if (pv < 1e-300) continue;   // free column
    if (pr != r)
      for (int jj = 0; jj < 9; jj++) { double t2 = A[r][jj]; A[r][jj] = A[pr][jj]; A[pr][jj] = t2; }
    double inv = 1.0 / A[r][c];
    for (int i2 = r + 1; i2 < 8; i2++) {
      double f = A[i2][c] * inv;
      for (int jj = c; jj < 9; jj++) A[i2][jj] -= f * A[r][jj];
    }
    pivcol[r] = c; isfree[c] = false; r++;
  }
  int fc = 8;
  for (int c = 8; c >= 0; c--) if (isfree[c]) fc = c;
  double h[9];
  for (int c = 0; c < 9; c++) h[c] = 0.0;
  h[fc] = 1.0;
  for (int i2 = r - 1; i2 >= 0; i2--) {
    int c = pivcol[i2];
    double sacc = 0.0;
    for (int jj = c + 1; jj < 9; jj++) sacc += A[i2][jj] * h[jj];
    h[c] = -sacc / A[i2][c];
  }
  // unit-normalize (matches SVD vector scale; eps-term then behaves like ref)
  double nrm = 0.0;
  for (int c = 0; c < 9; c++) nrm += h[c]*h[c];
  double inrm = 1.0 / sqrt(nrm);
  for (int c = 0; c < 9; c++) h[c] *= inrm;

  // H = inv(T2) * Hn * T1
  double M[9];
#pragma unroll
  for (int rr = 0; rr < 3; rr++) {
    double a = h[rr*3+0], b = h[rr*3+1], c = h[rr*3+2];
    M[rr*3+0] = a * s1;
    M[rr*3+1] = b * s1;
    M[rr*3+2] = -a*s1*m1x - b*s1*m1y + c;
  }
  double H[9];
  double is2 = 1.0 / s2;
#pragma unroll
  for (int c = 0; c < 3; c++) {
    H[0*3+c] = is2 * M[0*3+c] + m2x * M[2*3+c];
    H[1*3+c] = is2 * M[1*3+c] + m2y * M[2*3+c];
    H[2*3+c] = M[2*3+c];
  }
  double dv = H[8] + 1e-8;
  float Hf[9];
#pragma unroll
  for (int c = 0; c < 9; c++) Hf[c] = (float)(H[c] / dv);

  bool valid = (fabsf(Hf[0]) > 1e-6f) && (fabsf(Hf[4]) > 1e-6f) && (fabsf(Hf[8]) > 1e-6f);

  // Hinv from the float32 H (like reference: inv applied to final H)
  double a = Hf[0], b = Hf[1], c = Hf[2];
  double d = Hf[3], e = Hf[4], f = Hf[5];
  double g = Hf[6], hh = Hf[7], ii = Hf[8];
  double A11 = e*ii - f*hh, A12 = c*hh - b*ii, A13 = b*f - c*e;
  double A21 = f*g  - d*ii, A22 = a*ii - c*g,  A23 = c*d - a*f;
  double A31 = d*hh - e*g,  A32 = b*g  - a*hh, A33 = a*e - b*d;
  double det  = a*A11 + b*A21 + c*A31;
  double idet = 1.0 / det;
  float Hif[9] = {(float)(A11*idet), (float)(A12*idet), (float)(A13*idet),
                  (float)(A21*idet), (float)(A22*idet), (float)(A23*idet),
                  (float)(A31*idet), (float)(A32*idet), (float)(A33*idet)};

#pragma unroll
  for (int c2 = 0; c2 < 9; c2++) {
    g_H[m*9 + c2]    = Hf[c2];
    g_Hinv[m*9 + c2] = Hif[c2];
  }
  g_score[m] = valid ? 0 : -1;
}

// =====================================================================
// symmetric transfer error (f32, reference arithmetic incl. EPS mask)
// =====================================================================
__device__ __forceinline__ float terr(const float* H, float x, float y,
                                      float qx, float qy) {
  float X = fmaf(H[0], x, fmaf(H[1], y, H[2]));
  float Y = fmaf(H[3], x, fmaf(H[4], y, H[5]));
  float Z = fmaf(H[6], x, fmaf(H[7], y, H[8]));
  float s = (fabsf(Z) > 1e-8f) ? __fdiv_rn(1.0f, Z) : 1.0f;
  float dx = fmaf(X, s, -qx);
  float dy = fmaf(Y, s, -qy);
  return fmaf(dx, dx, dy * dy);
}

// =====================================================================
// Kernel 3: inlier count per model
// =====================================================================
__global__ __launch_bounds__(256) void k_score(const float2* __restrict__ kp1,
                                               const float2* __restrict__ kp2) {
  const int m   = blockIdx.x;
  const int tid = threadIdx.x;
  __shared__ float sH[9], sHi[9];
  if (tid < 9)                 sH[tid]       = g_H[m*9 + tid];
  if (tid >= 32 && tid < 41)   sHi[tid - 32] = g_Hinv[m*9 + (tid - 32)];
  __syncthreads();
  if (g_score[m] < 0) return;   // invalid model: keep -1 (uniform branch)

  int cnt = 0;
  for (int j = tid; j < N_PTS; j += 256) {
    float2 p = kp1[j], q = kp2[j];
    float e = terr(sH, p.x, p.y, q.x, q.y) + terr(sHi, q.x, q.y, p.x, p.y);
    cnt += (e <= 2.0f) ? 1 : 0;
  }
#pragma unroll
  for (int o = 16; o; o >>= 1) cnt += __shfl_down_sync(0xffffffffu, cnt, o);
  __shared__ int sw[8];
  if ((tid & 31) == 0) sw[tid >> 5] = cnt;
  __syncthreads();
  if (tid == 0) {
    int tot = 0;
    for (int w = 0; w < 8; w++) tot += sw[w];
    g_score[m] = tot;
  }
}

// =====================================================================
// Kernel 4: global best = max score, tie -> lowest model id; score > 1
// =====================================================================
__global__ __launch_bounds__(1024) void k_reduce() {
  __shared__ int bs[1024], bi[1024];
  const int tid = threadIdx.x;
  int mys = -2, myi = 0x7fffffff;
  for (int m = tid; m < NMODELS; m += 1024) {
    int s = g_score[m];
    if (s > mys || (s == mys && m < myi)) { mys = s; myi = m; }
  }
  bs[tid] = mys; bi[tid] = myi;
  __syncthreads();
  for (int s = 512; s >= 1; s >>= 1) {
    if (tid < s) {
      if (bs[tid+s] > bs[tid] || (bs[tid+s] == bs[tid] && bi[tid+s] < bi[tid])) {
        bs[tid] = bs[tid+s]; bi[tid] = bi[tid+s];
      }
    }
    __syncthreads();
  }
  if (tid == 0) g_bestid = (bs[0] >= 2) ? bi[0] : -1;  // must beat init 1.0
}

// =====================================================================
// Kernel 5: write output [H(9), inlier mask(10000)] as float32
// =====================================================================
__global__ __launch_bounds__(256) void k_out(const float2* __restrict__ kp1,
                                             const float2* __restrict__ kp2,
                                             float* __restrict__ out,
                                             int out_size) {
  const int t = blockIdx.x * blockDim.x + threadIdx.x;
  if (t >= out_size) return;
  const int best = g_bestid;
  if (t < 9) {
    out[t] = (best >= 0) ? g_H[best*9 + t]
                         : ((t == 0 || t == 4 || t == 8) ? 1.0f : 0.0f);
  } else if (t < 9 + N_PTS) {
    int j = t - 9;
    float r = 0.0f;
    if (best >= 0) {
      float H[9], Hi[9];
#pragma unroll
      for (int c = 0; c < 9; c++) { H[c] = g_H[best*9+c]; Hi[c] = g_Hinv[best*9+c]; }
      float2 p = kp1[j], q = kp2[j];
      float e = terr(H, p.x, p.y, q.x, q.y) + terr(Hi, q.x, q.y, p.x, p.y);
      r = (e <= 2.0f) ? 1.0f : 0.0f;
    }
    out[t] = r;
  } else {
    out[t] = 0.0f;
  }
}

// =====================================================================
extern "C" void kernel_launch(void* const* d_in, const int* in_sizes, int n_in,
                              void* d_out, int out_size) {
  const float* kp1 = (const float*)d_in[0];
  const float* kp2 = (const float*)d_in[1];
  float* out = (float*)d_out;

  // derive the 10 iteration keys from jax.random.key(42) on host
  KeyList keys;
#if JAX_PARTITIONABLE
  for (int j = 0; j < MAX_ITER; j++) {
    uint32_t a, b;
    tf2x32(0u, 42u, 0u, (uint32_t)j, a, b);   // foldlike split: counts (0, j)
    keys.k0[j] = a; keys.k1[j] = b;
  }
#else
  uint32_t flat[2 * MAX_ITER];
  for (int i = 0; i < MAX_ITER; i++) {
    uint32_t a, b;
    tf2x32(0u, 42u, (uint32_t)i, (uint32_t)(i + MAX_ITER), a, b);
    flat[i] = a; flat[MAX_ITER + i] = b;
  }
  for (int j = 0; j < MAX_ITER; j++) { keys.k0[j] = flat[2*j]; keys.k1[j] = flat[2*j+1]; }
#endif

  k_sample<<<dim3(BATCH, MAX_ITER), 256>>>(keys);
  k_dlt<<<(NMODELS + 127) / 128, 128>>>(kp1, kp2);
  k_score<<<NMODELS, 256>>>((const float2*)kp1, (const float2*)kp2);
  k_reduce<<<1, 1024>>>();
  int nt = out_size > 0 ? out_size : 1;
  k_out<<<(nt + 255) / 256, 256>>>((const float2*)kp1, (const float2*)kp2, out, out_size);
}